// round 1
// baseline (speedup 1.0000x reference)
#include <cuda_runtime.h>
#include <math.h>

#define N_EMBED 1024
#define SLEN    2048
#define BATCH   4
#define NHEADS  16
#define HDIM    64
#define MROWS   (BATCH * SLEN)        // 8192

// Scratch (device globals: allocation-free rule)
__device__ float g_qkv[(size_t)MROWS * 3 * N_EMBED];  // [8192, 3072]
__device__ float g_y[(size_t)MROWS * N_EMBED];        // [8192, 1024]

// ---------------------------------------------------------------------------
// SGEMM: C[M,N] = A[M,K] @ B[K,N] + bias[N]
// BM=BN=128, BK=16, 256 threads, 8x8 micro-tile. All dims divide tiles.
// ---------------------------------------------------------------------------
__global__ __launch_bounds__(256)
void sgemm_bias_kernel(const float* __restrict__ A, const float* __restrict__ B,
                       const float* __restrict__ bias, float* __restrict__ C,
                       int M, int N, int K) {
    constexpr int BM = 128, BN = 128, BK = 16, TM = 8, TN = 8;
    __shared__ float As[BK][BM];
    __shared__ float Bs[BK][BN];

    const int tid  = threadIdx.x;
    const int row0 = blockIdx.y * BM;
    const int col0 = blockIdx.x * BN;
    const int tr   = tid / (BN / TN);   // 0..15
    const int tc   = tid % (BN / TN);   // 0..15

    float acc[TM][TN];
    #pragma unroll
    for (int i = 0; i < TM; i++)
        #pragma unroll
        for (int j = 0; j < TN; j++) acc[i][j] = 0.f;

    const int aRow = tid / 4;          // 0..63
    const int aCol = (tid % 4) * 4;    // 0,4,8,12
    const int bRow = tid / 32;         // 0..7
    const int bCol = (tid % 32) * 4;   // 0..124

    for (int k0 = 0; k0 < K; k0 += BK) {
        // Load A tile (128x16), transposed into As[k][m]
        #pragma unroll
        for (int i = 0; i < BM; i += 64) {
            float4 v = *reinterpret_cast<const float4*>(
                &A[(size_t)(row0 + aRow + i) * K + k0 + aCol]);
            As[aCol + 0][aRow + i] = v.x;
            As[aCol + 1][aRow + i] = v.y;
            As[aCol + 2][aRow + i] = v.z;
            As[aCol + 3][aRow + i] = v.w;
        }
        // Load B tile (16x128)
        #pragma unroll
        for (int i = 0; i < BK; i += 8) {
            float4 v = *reinterpret_cast<const float4*>(
                &B[(size_t)(k0 + bRow + i) * N + col0 + bCol]);
            *reinterpret_cast<float4*>(&Bs[bRow + i][bCol]) = v;
        }
        __syncthreads();

        #pragma unroll
        for (int k = 0; k < BK; k++) {
            float ra[TM], rb[TN];
            #pragma unroll
            for (int i = 0; i < TM; i++) ra[i] = As[k][tr * TM + i];
            #pragma unroll
            for (int j = 0; j < TN; j++) rb[j] = Bs[k][tc * TN + j];
            #pragma unroll
            for (int i = 0; i < TM; i++)
                #pragma unroll
                for (int j = 0; j < TN; j++)
                    acc[i][j] += ra[i] * rb[j];
        }
        __syncthreads();
    }

    #pragma unroll
    for (int i = 0; i < TM; i++) {
        const size_t r = row0 + tr * TM + i;
        #pragma unroll
        for (int j = 0; j < TN; j += 4) {
            const int c = col0 + tc * TN + j;
            float4 v;
            v.x = acc[i][j + 0] + bias[c + 0];
            v.y = acc[i][j + 1] + bias[c + 1];
            v.z = acc[i][j + 2] + bias[c + 2];
            v.w = acc[i][j + 3] + bias[c + 3];
            *reinterpret_cast<float4*>(&C[r * N + c]) = v;
        }
    }
}

// ---------------------------------------------------------------------------
// Flash attention (causal). One block = (q-tile of 64 rows, head, batch).
// 64 threads, 1 q row per thread (q in registers). K/V streamed in 32-row
// chunks through SMEM; online softmax. Reads g_qkv [8192, 3072] where
// Q = cols [0,1024), K = [1024,2048), V = [2048,3072), head h at h*64.
// Writes g_y [8192, 1024] (heads re-interleaved).
// ---------------------------------------------------------------------------
__global__ __launch_bounds__(64)
void flash_attn_kernel(const float* __restrict__ qkv, float* __restrict__ y) {
    const int qt  = blockIdx.x;   // 0..31
    const int h   = blockIdx.y;   // 0..15
    const int b   = blockIdx.z;   // 0..3
    const int tid = threadIdx.x;  // 0..63
    const int qg  = qt * 64 + tid;

    __shared__ float Ks[32][HDIM];
    __shared__ float Vs[32][HDIM];

    // Load q row into registers
    float qreg[HDIM];
    const float* qptr = qkv + ((size_t)(b * SLEN + qg)) * (3 * N_EMBED) + h * HDIM;
    #pragma unroll
    for (int d = 0; d < HDIM; d += 4) {
        float4 v = *reinterpret_cast<const float4*>(qptr + d);
        qreg[d] = v.x; qreg[d + 1] = v.y; qreg[d + 2] = v.z; qreg[d + 3] = v.w;
    }

    const float scale = 0.125f;   // 1/sqrt(64)
    float m = -INFINITY, l = 0.f;
    float acc[HDIM];
    #pragma unroll
    for (int d = 0; d < HDIM; d++) acc[d] = 0.f;

    const int kmax = qt * 64 + 63;   // largest key any row of this tile sees
    for (int kb = 0; kb <= kmax; kb += 32) {
        // Cooperative load of K/V chunk: 32 rows x 64 cols
        #pragma unroll
        for (int i = 0; i < 8; i++) {
            const int lin = i * 256 + tid * 4;
            const int r = lin >> 6, c = lin & 63;
            const float* kp = qkv + ((size_t)(b * SLEN + kb + r)) * (3 * N_EMBED)
                              + N_EMBED + h * HDIM + c;
            *reinterpret_cast<float4*>(&Ks[r][c]) = *reinterpret_cast<const float4*>(kp);
            *reinterpret_cast<float4*>(&Vs[r][c]) = *reinterpret_cast<const float4*>(kp + N_EMBED);
        }
        __syncthreads();

        // Scores for 32 keys
        float s[32];
        #pragma unroll
        for (int j = 0; j < 32; j++) {
            float dot = 0.f;
            #pragma unroll
            for (int d = 0; d < HDIM; d++) dot += qreg[d] * Ks[j][d];
            const int kg = kb + j;
            s[j] = (kg <= qg) ? dot * scale : -INFINITY;
        }

        // Online softmax update
        float mt = m;
        #pragma unroll
        for (int j = 0; j < 32; j++) mt = fmaxf(mt, s[j]);
        const float alpha = __expf(m - mt);
        float psum = 0.f;
        #pragma unroll
        for (int j = 0; j < 32; j++) { s[j] = __expf(s[j] - mt); psum += s[j]; }
        l = l * alpha + psum;
        #pragma unroll
        for (int d = 0; d < HDIM; d++) acc[d] *= alpha;
        #pragma unroll
        for (int j = 0; j < 32; j++) {
            const float pj = s[j];
            #pragma unroll
            for (int d = 0; d < HDIM; d++) acc[d] += pj * Vs[j][d];
        }
        m = mt;
        __syncthreads();
    }

    const float inv = 1.f / l;
    float* yp = y + ((size_t)(b * SLEN + qg)) * N_EMBED + h * HDIM;
    #pragma unroll
    for (int d = 0; d < HDIM; d += 4) {
        float4 v;
        v.x = acc[d] * inv; v.y = acc[d + 1] * inv;
        v.z = acc[d + 2] * inv; v.w = acc[d + 3] * inv;
        *reinterpret_cast<float4*>(yp + d) = v;
    }
}

// ---------------------------------------------------------------------------
// kernel_launch
// Inputs: x [4,2048,1024], W_attn [1024,3072], b_attn [3072],
//         W_proj [1024,1024], b_proj [1024].  Output: [4,2048,1024] f32.
// ---------------------------------------------------------------------------
extern "C" void kernel_launch(void* const* d_in, const int* in_sizes, int n_in,
                              void* d_out, int out_size) {
    const float* x      = (const float*)d_in[0];
    const float* W_attn = (const float*)d_in[1];
    const float* b_attn = (const float*)d_in[2];
    const float* W_proj = (const float*)d_in[3];
    const float* b_proj = (const float*)d_in[4];
    float* out = (float*)d_out;

    float* qkv = nullptr;
    float* yb  = nullptr;
    cudaGetSymbolAddress((void**)&qkv, g_qkv);
    cudaGetSymbolAddress((void**)&yb,  g_y);

    // 1) QKV GEMM: [8192,1024] @ [1024,3072] + b_attn -> g_qkv
    {
        dim3 grid(3 * N_EMBED / 128, MROWS / 128);
        sgemm_bias_kernel<<<grid, 256>>>(x, W_attn, b_attn, qkv,
                                         MROWS, 3 * N_EMBED, N_EMBED);
    }
    // 2) Causal flash attention -> g_y
    {
        dim3 grid(SLEN / 64, NHEADS, BATCH);
        flash_attn_kernel<<<grid, 64>>>(qkv, yb);
    }
    // 3) Output projection: [8192,1024] @ [1024,1024] + b_proj -> out
    {
        dim3 grid(N_EMBED / 128, MROWS / 128);
        sgemm_bias_kernel<<<grid, 256>>>(yb, W_proj, b_proj, out,
                                         MROWS, N_EMBED, N_EMBED);
    }
}

// round 3
// speedup vs baseline: 1.4081x; 1.4081x over previous
#include <cuda_runtime.h>
#include <math.h>
#include <stdint.h>

#define N_EMBED 1024
#define SLEN    2048
#define BATCH   4
#define NHEADS  16
#define HDIM    64
#define MROWS   (BATCH * SLEN)        // 8192

// Scratch (device globals: allocation-free rule)
__device__ float g_qkv[(size_t)MROWS * 3 * N_EMBED];  // [8192, 3072]
__device__ float g_y[(size_t)MROWS * N_EMBED];        // [8192, 1024]

// ---------------------------------------------------------------------------
// Helpers
// ---------------------------------------------------------------------------
__device__ __forceinline__ uint32_t f2tf32(float f) {
    uint32_t r;
    asm("cvt.rna.tf32.f32 %0, %1;" : "=r"(r) : "f"(f));
    return r;
}
__device__ __forceinline__ void mma_tf32(float d[4], const uint32_t a[4], const uint32_t b[2]) {
    asm volatile(
        "mma.sync.aligned.m16n8k8.row.col.f32.tf32.tf32.f32 "
        "{%0,%1,%2,%3}, {%4,%5,%6,%7}, {%8,%9}, {%0,%1,%2,%3};"
        : "+f"(d[0]), "+f"(d[1]), "+f"(d[2]), "+f"(d[3])
        : "r"(a[0]), "r"(a[1]), "r"(a[2]), "r"(a[3]), "r"(b[0]), "r"(b[1]));
}

// ---------------------------------------------------------------------------
// tf32 mma.sync GEMM: C[M,N] = A[M,K] @ B[K,N] + bias[N]
// BM=BN=128, BK=16, 256 threads (8 warps, 2x4), warp tile 64x32,
// double-buffered smem. M,N,K multiples of tile dims.
//   A smem: As[128][20] (pad 16->20, conflict-free frag reads, float4-aligned)
//   B smem: Bs[16][136]  (pad 128->136)
// ---------------------------------------------------------------------------
__global__ __launch_bounds__(256)
void mma_gemm_kernel(const float* __restrict__ A, const float* __restrict__ B,
                     const float* __restrict__ bias, float* __restrict__ C,
                     int M, int N, int K) {
    constexpr int AS = 20, BS = 136;
    __shared__ uint32_t As[2][128 * AS];
    __shared__ uint32_t Bs[2][16 * BS];

    const int tid   = threadIdx.x;
    const int lane  = tid & 31;
    const int wid   = tid >> 5;
    const int gid   = lane >> 2;          // 0..7
    const int tig   = lane & 3;           // 0..3
    const int warpM = wid >> 2;           // 0..1 -> 64 rows
    const int warpN = wid & 3;            // 0..3 -> 32 cols
    const int row0  = blockIdx.y * 128;
    const int col0  = blockIdx.x * 128;

    float acc[4][4][4];
    #pragma unroll
    for (int i = 0; i < 4; i++)
        #pragma unroll
        for (int j = 0; j < 4; j++)
            #pragma unroll
            for (int r = 0; r < 4; r++) acc[i][j][r] = 0.f;

    float4 av[2], bv[2];
    const int NT = K / 16;

    // --- tile load (global -> regs) ---
    auto load_tile = [&](int kt) {
        #pragma unroll
        for (int i = 0; i < 2; i++) {
            const int f = tid + i * 256;
            const int arow = f >> 2, aj = f & 3;
            av[i] = *reinterpret_cast<const float4*>(
                A + (size_t)(row0 + arow) * K + kt * 16 + aj * 4);
            const int brow = f >> 5, bj = f & 31;
            bv[i] = *reinterpret_cast<const float4*>(
                B + (size_t)(kt * 16 + brow) * N + col0 + bj * 4);
        }
    };
    // --- regs -> smem (with tf32 conversion) ---
    auto store_tile = [&](int buf) {
        #pragma unroll
        for (int i = 0; i < 2; i++) {
            const int f = tid + i * 256;
            const int arow = f >> 2, aj = f & 3;
            uint32_t* ap = &As[buf][arow * AS + aj * 4];
            ap[0] = f2tf32(av[i].x); ap[1] = f2tf32(av[i].y);
            ap[2] = f2tf32(av[i].z); ap[3] = f2tf32(av[i].w);
            const int brow = f >> 5, bj = f & 31;
            uint32_t* bp = &Bs[buf][brow * BS + bj * 4];
            bp[0] = f2tf32(bv[i].x); bp[1] = f2tf32(bv[i].y);
            bp[2] = f2tf32(bv[i].z); bp[3] = f2tf32(bv[i].w);
        }
    };
    // --- compute one BK=16 tile from smem ---
    auto compute = [&](int buf) {
        #pragma unroll
        for (int ks = 0; ks < 2; ks++) {
            const int kb = ks * 8;
            uint32_t a[4][4], b[4][2];
            #pragma unroll
            for (int mf = 0; mf < 4; mf++) {
                const int r = warpM * 64 + mf * 16;
                a[mf][0] = As[buf][(r + gid)     * AS + kb + tig];
                a[mf][1] = As[buf][(r + gid + 8) * AS + kb + tig];
                a[mf][2] = As[buf][(r + gid)     * AS + kb + tig + 4];
                a[mf][3] = As[buf][(r + gid + 8) * AS + kb + tig + 4];
            }
            #pragma unroll
            for (int nf = 0; nf < 4; nf++) {
                const int c = warpN * 32 + nf * 8 + gid;
                b[nf][0] = Bs[buf][(kb + tig)     * BS + c];
                b[nf][1] = Bs[buf][(kb + tig + 4) * BS + c];
            }
            #pragma unroll
            for (int mf = 0; mf < 4; mf++)
                #pragma unroll
                for (int nf = 0; nf < 4; nf++)
                    mma_tf32(acc[mf][nf], a[mf], b[nf]);
        }
    };

    load_tile(0);
    store_tile(0);
    __syncthreads();

    for (int kt = 0; kt < NT; kt++) {
        const int cur = kt & 1;
        const bool more = (kt + 1) < NT;
        if (more) load_tile(kt + 1);
        compute(cur);
        if (more) store_tile(cur ^ 1);
        __syncthreads();
    }

    // Epilogue: add bias, store fp32
    #pragma unroll
    for (int mf = 0; mf < 4; mf++) {
        const size_t rbase = (size_t)row0 + warpM * 64 + mf * 16 + gid;
        #pragma unroll
        for (int nf = 0; nf < 4; nf++) {
            const int col = col0 + warpN * 32 + nf * 8 + tig * 2;
            const float2 bz = *reinterpret_cast<const float2*>(bias + col);
            float2 v0, v1;
            v0.x = acc[mf][nf][0] + bz.x; v0.y = acc[mf][nf][1] + bz.y;
            v1.x = acc[mf][nf][2] + bz.x; v1.y = acc[mf][nf][3] + bz.y;
            *reinterpret_cast<float2*>(C + rbase * N + col)       = v0;
            *reinterpret_cast<float2*>(C + (rbase + 8) * N + col) = v1;
        }
    }
}

// ---------------------------------------------------------------------------
// Flash attention (causal) — unchanged (correct, target for next round).
// ---------------------------------------------------------------------------
__global__ __launch_bounds__(64)
void flash_attn_kernel(const float* __restrict__ qkv, float* __restrict__ y) {
    const int qt  = blockIdx.x;
    const int h   = blockIdx.y;
    const int b   = blockIdx.z;
    const int tid = threadIdx.x;
    const int qg  = qt * 64 + tid;

    __shared__ float Ks[32][HDIM];
    __shared__ float Vs[32][HDIM];

    float qreg[HDIM];
    const float* qptr = qkv + ((size_t)(b * SLEN + qg)) * (3 * N_EMBED) + h * HDIM;
    #pragma unroll
    for (int d = 0; d < HDIM; d += 4) {
        float4 v = *reinterpret_cast<const float4*>(qptr + d);
        qreg[d] = v.x; qreg[d + 1] = v.y; qreg[d + 2] = v.z; qreg[d + 3] = v.w;
    }

    const float scale = 0.125f;
    float m = -INFINITY, l = 0.f;
    float acc[HDIM];
    #pragma unroll
    for (int d = 0; d < HDIM; d++) acc[d] = 0.f;

    const int kmax = qt * 64 + 63;
    for (int kb = 0; kb <= kmax; kb += 32) {
        #pragma unroll
        for (int i = 0; i < 8; i++) {
            const int lin = i * 256 + tid * 4;
            const int r = lin >> 6, c = lin & 63;
            const float* kp = qkv + ((size_t)(b * SLEN + kb + r)) * (3 * N_EMBED)
                              + N_EMBED + h * HDIM + c;
            *reinterpret_cast<float4*>(&Ks[r][c]) = *reinterpret_cast<const float4*>(kp);
            *reinterpret_cast<float4*>(&Vs[r][c]) = *reinterpret_cast<const float4*>(kp + N_EMBED);
        }
        __syncthreads();

        float s[32];
        #pragma unroll
        for (int j = 0; j < 32; j++) {
            float dot = 0.f;
            #pragma unroll
            for (int d = 0; d < HDIM; d++) dot += qreg[d] * Ks[j][d];
            const int kg = kb + j;
            s[j] = (kg <= qg) ? dot * scale : -INFINITY;
        }

        float mt = m;
        #pragma unroll
        for (int j = 0; j < 32; j++) mt = fmaxf(mt, s[j]);
        const float alpha = __expf(m - mt);
        float psum = 0.f;
        #pragma unroll
        for (int j = 0; j < 32; j++) { s[j] = __expf(s[j] - mt); psum += s[j]; }
        l = l * alpha + psum;
        #pragma unroll
        for (int d = 0; d < HDIM; d++) acc[d] *= alpha;
        #pragma unroll
        for (int j = 0; j < 32; j++) {
            const float pj = s[j];
            #pragma unroll
            for (int d = 0; d < HDIM; d++) acc[d] += pj * Vs[j][d];
        }
        m = mt;
        __syncthreads();
    }

    const float inv = 1.f / l;
    float* yp = y + ((size_t)(b * SLEN + qg)) * N_EMBED + h * HDIM;
    #pragma unroll
    for (int d = 0; d < HDIM; d += 4) {
        float4 v;
        v.x = acc[d] * inv; v.y = acc[d + 1] * inv;
        v.z = acc[d + 2] * inv; v.w = acc[d + 3] * inv;
        *reinterpret_cast<float4*>(yp + d) = v;
    }
}

// ---------------------------------------------------------------------------
// kernel_launch
// ---------------------------------------------------------------------------
extern "C" void kernel_launch(void* const* d_in, const int* in_sizes, int n_in,
                              void* d_out, int out_size) {
    const float* x      = (const float*)d_in[0];
    const float* W_attn = (const float*)d_in[1];
    const float* b_attn = (const float*)d_in[2];
    const float* W_proj = (const float*)d_in[3];
    const float* b_proj = (const float*)d_in[4];
    float* out = (float*)d_out;

    float* qkv = nullptr; float* yb = nullptr;
    cudaGetSymbolAddress((void**)&qkv, g_qkv);
    cudaGetSymbolAddress((void**)&yb,  g_y);

    // 1) QKV GEMM (tf32 mma.sync): [8192,1024] @ [1024,3072] + b_attn
    {
        dim3 grid(3 * N_EMBED / 128, MROWS / 128);
        mma_gemm_kernel<<<grid, 256>>>(x, W_attn, b_attn, qkv, MROWS, 3 * N_EMBED, N_EMBED);
    }
    // 2) Causal flash attention
    {
        dim3 grid(SLEN / 64, NHEADS, BATCH);
        flash_attn_kernel<<<grid, 64>>>(qkv, yb);
    }
    // 3) Output projection (tf32 mma.sync): [8192,1024] @ [1024,1024] + b_proj
    {
        dim3 grid(N_EMBED / 128, MROWS / 128);
        mma_gemm_kernel<<<grid, 256>>>(yb, W_proj, b_proj, out, MROWS, N_EMBED, N_EMBED);
    }
}

// round 4
// speedup vs baseline: 3.3948x; 2.4110x over previous
#include <cuda_runtime.h>
#include <math.h>
#include <stdint.h>

#define N_EMBED 1024
#define SLEN    2048
#define BATCH   4
#define NHEADS  16
#define HDIM    64
#define MROWS   (BATCH * SLEN)        // 8192

// Scratch (device globals: allocation-free rule)
__device__ float g_qkv[(size_t)MROWS * 3 * N_EMBED];  // [8192, 3072]
__device__ float g_y[(size_t)MROWS * N_EMBED];        // [8192, 1024]

// ---------------------------------------------------------------------------
// Helpers
// ---------------------------------------------------------------------------
__device__ __forceinline__ uint32_t f2tf32(float f) {
    uint32_t r;
    asm("cvt.rna.tf32.f32 %0, %1;" : "=r"(r) : "f"(f));
    return r;
}
__device__ __forceinline__ void mma_tf32(float d[4], const uint32_t a[4], const uint32_t b[2]) {
    asm volatile(
        "mma.sync.aligned.m16n8k8.row.col.f32.tf32.tf32.f32 "
        "{%0,%1,%2,%3}, {%4,%5,%6,%7}, {%8,%9}, {%0,%1,%2,%3};"
        : "+f"(d[0]), "+f"(d[1]), "+f"(d[2]), "+f"(d[3])
        : "r"(a[0]), "r"(a[1]), "r"(a[2]), "r"(a[3]), "r"(b[0]), "r"(b[1]));
}

// ---------------------------------------------------------------------------
// tf32 mma.sync GEMM: C[M,N] = A[M,K] @ B[K,N] + bias[N]  (unchanged from R3)
// ---------------------------------------------------------------------------
__global__ __launch_bounds__(256)
void mma_gemm_kernel(const float* __restrict__ A, const float* __restrict__ B,
                     const float* __restrict__ bias, float* __restrict__ C,
                     int M, int N, int K) {
    constexpr int AS = 20, BS = 136;
    __shared__ uint32_t As[2][128 * AS];
    __shared__ uint32_t Bs[2][16 * BS];

    const int tid   = threadIdx.x;
    const int lane  = tid & 31;
    const int wid   = tid >> 5;
    const int gid   = lane >> 2;
    const int tig   = lane & 3;
    const int warpM = wid >> 2;
    const int warpN = wid & 3;
    const int row0  = blockIdx.y * 128;
    const int col0  = blockIdx.x * 128;

    float acc[4][4][4];
    #pragma unroll
    for (int i = 0; i < 4; i++)
        #pragma unroll
        for (int j = 0; j < 4; j++)
            #pragma unroll
            for (int r = 0; r < 4; r++) acc[i][j][r] = 0.f;

    float4 av[2], bv[2];
    const int NT = K / 16;

    auto load_tile = [&](int kt) {
        #pragma unroll
        for (int i = 0; i < 2; i++) {
            const int f = tid + i * 256;
            const int arow = f >> 2, aj = f & 3;
            av[i] = *reinterpret_cast<const float4*>(
                A + (size_t)(row0 + arow) * K + kt * 16 + aj * 4);
            const int brow = f >> 5, bj = f & 31;
            bv[i] = *reinterpret_cast<const float4*>(
                B + (size_t)(kt * 16 + brow) * N + col0 + bj * 4);
        }
    };
    auto store_tile = [&](int buf) {
        #pragma unroll
        for (int i = 0; i < 2; i++) {
            const int f = tid + i * 256;
            const int arow = f >> 2, aj = f & 3;
            uint32_t* ap = &As[buf][arow * AS + aj * 4];
            ap[0] = f2tf32(av[i].x); ap[1] = f2tf32(av[i].y);
            ap[2] = f2tf32(av[i].z); ap[3] = f2tf32(av[i].w);
            const int brow = f >> 5, bj = f & 31;
            uint32_t* bp = &Bs[buf][brow * BS + bj * 4];
            bp[0] = f2tf32(bv[i].x); bp[1] = f2tf32(bv[i].y);
            bp[2] = f2tf32(bv[i].z); bp[3] = f2tf32(bv[i].w);
        }
    };
    auto compute = [&](int buf) {
        #pragma unroll
        for (int ks = 0; ks < 2; ks++) {
            const int kb = ks * 8;
            uint32_t a[4][4], b[4][2];
            #pragma unroll
            for (int mf = 0; mf < 4; mf++) {
                const int r = warpM * 64 + mf * 16;
                a[mf][0] = As[buf][(r + gid)     * AS + kb + tig];
                a[mf][1] = As[buf][(r + gid + 8) * AS + kb + tig];
                a[mf][2] = As[buf][(r + gid)     * AS + kb + tig + 4];
                a[mf][3] = As[buf][(r + gid + 8) * AS + kb + tig + 4];
            }
            #pragma unroll
            for (int nf = 0; nf < 4; nf++) {
                const int c = warpN * 32 + nf * 8 + gid;
                b[nf][0] = Bs[buf][(kb + tig)     * BS + c];
                b[nf][1] = Bs[buf][(kb + tig + 4) * BS + c];
            }
            #pragma unroll
            for (int mf = 0; mf < 4; mf++)
                #pragma unroll
                for (int nf = 0; nf < 4; nf++)
                    mma_tf32(acc[mf][nf], a[mf], b[nf]);
        }
    };

    load_tile(0);
    store_tile(0);
    __syncthreads();

    for (int kt = 0; kt < NT; kt++) {
        const int cur = kt & 1;
        const bool more = (kt + 1) < NT;
        if (more) load_tile(kt + 1);
        compute(cur);
        if (more) store_tile(cur ^ 1);
        __syncthreads();
    }

    #pragma unroll
    for (int mf = 0; mf < 4; mf++) {
        const size_t rbase = (size_t)row0 + warpM * 64 + mf * 16 + gid;
        #pragma unroll
        for (int nf = 0; nf < 4; nf++) {
            const int col = col0 + warpN * 32 + nf * 8 + tig * 2;
            const float2 bz = *reinterpret_cast<const float2*>(bias + col);
            float2 v0, v1;
            v0.x = acc[mf][nf][0] + bz.x; v0.y = acc[mf][nf][1] + bz.y;
            v1.x = acc[mf][nf][2] + bz.x; v1.y = acc[mf][nf][3] + bz.y;
            *reinterpret_cast<float2*>(C + rbase * N + col)       = v0;
            *reinterpret_cast<float2*>(C + (rbase + 8) * N + col) = v1;
        }
    }
}

// ---------------------------------------------------------------------------
// Flash attention, tensor-core version.
// CTA = (q-tile of 128 rows) x head x batch.  8 warps, 16 q-rows per warp.
// Key chunks of 64 through SMEM. QK^T in 3-term tf32 split (fp32-accurate),
// PV in plain tf32. Online softmax on register fragments.
// SMEM (dynamic, word layout, stride 76 everywhere — conflict-free frags):
//   chunk region: Khi[64*76] Klo[64*76] Vs[64*76] Ps[128*76]  (24320 words)
//   Q staging (overlaid, used before first chunk): Qhi[128*76] Qlo[128*76]
// ---------------------------------------------------------------------------
#define STR 76

__global__ __launch_bounds__(256)
void flash_attn_mma_kernel(const float* __restrict__ qkv, float* __restrict__ y) {
    extern __shared__ uint32_t sm[];
    uint32_t* Khi = sm;                      // 64*76
    uint32_t* Klo = sm + 64 * STR;           // 64*76
    uint32_t* Vs  = sm + 128 * STR;          // 64*76
    uint32_t* Ps  = sm + 192 * STR;          // 128*76
    uint32_t* Qhi = sm;                      // staging overlay: 128*76
    uint32_t* Qlo = sm + 128 * STR;          // staging overlay: 128*76

    const int qt  = blockIdx.x;
    const int h   = blockIdx.y;
    const int b   = blockIdx.z;
    const int tid = threadIdx.x;
    const int lane = tid & 31;
    const int wid  = tid >> 5;
    const int gid  = lane >> 2;   // 0..7
    const int tig  = lane & 3;    // 0..3
    const int q0   = qt * 128;
    const int wrow = wid * 16;
    const size_t rowbase = (size_t)b * SLEN;

    // ---- Stage Q tile (scaled by 1/8, hi/lo tf32 split) ----
    #pragma unroll
    for (int it = 0; it < 8; it++) {
        const int idx = it * 256 + tid;       // 2048 float4
        const int r = idx >> 4, c4 = idx & 15;
        const float* qp = qkv + (rowbase + q0 + r) * 3072 + h * 64 + c4 * 4;
        const float4 v = *reinterpret_cast<const float4*>(qp);
        const float f[4] = {v.x * 0.125f, v.y * 0.125f, v.z * 0.125f, v.w * 0.125f};
        #pragma unroll
        for (int j = 0; j < 4; j++) {
            const uint32_t hi = f2tf32(f[j]);
            Qhi[r * STR + c4 * 4 + j] = hi;
            Qlo[r * STR + c4 * 4 + j] = f2tf32(f[j] - __uint_as_float(hi));
        }
    }
    __syncthreads();

    // ---- Q fragments into registers (16 rows x 64 dims per warp) ----
    uint32_t qh[8][4], ql[8][4];
    #pragma unroll
    for (int kk = 0; kk < 8; kk++) {
        const int ba = (wrow + gid) * STR + kk * 8;
        const int bb = (wrow + gid + 8) * STR + kk * 8;
        qh[kk][0] = Qhi[ba + tig];     qh[kk][1] = Qhi[bb + tig];
        qh[kk][2] = Qhi[ba + tig + 4]; qh[kk][3] = Qhi[bb + tig + 4];
        ql[kk][0] = Qlo[ba + tig];     ql[kk][1] = Qlo[bb + tig];
        ql[kk][2] = Qlo[ba + tig + 4]; ql[kk][3] = Qlo[bb + tig + 4];
    }

    float oacc[8][4];
    #pragma unroll
    for (int nf = 0; nf < 8; nf++)
        #pragma unroll
        for (int e = 0; e < 4; e++) oacc[nf][e] = 0.f;
    float m0 = -INFINITY, m1 = -INFINITY, l0 = 0.f, l1 = 0.f;

    const int row0g = q0 + wrow + gid;
    const int row1g = row0g + 8;
    const int kend  = q0 + 128;

    for (int kb = 0; kb < kend; kb += 64) {
        __syncthreads();   // protect K/V/P region from overwrite (and Q staging, first iter)

        // ---- load K/V chunk: 64 rows x 64 dims ----
        #pragma unroll
        for (int it = 0; it < 4; it++) {
            const int idx = it * 256 + tid;    // 1024 float4
            const int r = idx >> 4, c4 = idx & 15;
            const float* kp = qkv + (rowbase + kb + r) * 3072 + N_EMBED + h * 64 + c4 * 4;
            const float4 kv = *reinterpret_cast<const float4*>(kp);
            const float4 vv = *reinterpret_cast<const float4*>(kp + N_EMBED);
            const float kf[4] = {kv.x, kv.y, kv.z, kv.w};
            const float vf[4] = {vv.x, vv.y, vv.z, vv.w};
            #pragma unroll
            for (int j = 0; j < 4; j++) {
                const uint32_t hi = f2tf32(kf[j]);
                Khi[r * STR + c4 * 4 + j] = hi;
                Klo[r * STR + c4 * 4 + j] = f2tf32(kf[j] - __uint_as_float(hi));
                Vs [r * STR + c4 * 4 + j] = f2tf32(vf[j]);
            }
        }
        __syncthreads();

        // ---- S = Q K^T (3-term split) ----
        float sacc[8][4];
        #pragma unroll
        for (int nf = 0; nf < 8; nf++)
            #pragma unroll
            for (int e = 0; e < 4; e++) sacc[nf][e] = 0.f;

        #pragma unroll
        for (int kk = 0; kk < 8; kk++) {
            #pragma unroll
            for (int nf = 0; nf < 8; nf++) {
                const int kr = (nf * 8 + gid) * STR + kk * 8;
                uint32_t bh[2], bl[2];
                bh[0] = Khi[kr + tig]; bh[1] = Khi[kr + tig + 4];
                bl[0] = Klo[kr + tig]; bl[1] = Klo[kr + tig + 4];
                mma_tf32(sacc[nf], qh[kk], bh);
                mma_tf32(sacc[nf], ql[kk], bh);
                mma_tf32(sacc[nf], qh[kk], bl);
            }
        }

        // ---- causal mask (diagonal chunks only) ----
        if (kb + 63 > q0 + wrow) {
            #pragma unroll
            for (int nf = 0; nf < 8; nf++) {
                const int c = kb + nf * 8 + tig * 2;
                if (c     > row0g) sacc[nf][0] = -INFINITY;
                if (c + 1 > row0g) sacc[nf][1] = -INFINITY;
                if (c     > row1g) sacc[nf][2] = -INFINITY;
                if (c + 1 > row1g) sacc[nf][3] = -INFINITY;
            }
        }

        // ---- online softmax ----
        float mx0 = -INFINITY, mx1 = -INFINITY;
        #pragma unroll
        for (int nf = 0; nf < 8; nf++) {
            mx0 = fmaxf(mx0, fmaxf(sacc[nf][0], sacc[nf][1]));
            mx1 = fmaxf(mx1, fmaxf(sacc[nf][2], sacc[nf][3]));
        }
        mx0 = fmaxf(mx0, __shfl_xor_sync(0xffffffff, mx0, 1));
        mx0 = fmaxf(mx0, __shfl_xor_sync(0xffffffff, mx0, 2));
        mx1 = fmaxf(mx1, __shfl_xor_sync(0xffffffff, mx1, 1));
        mx1 = fmaxf(mx1, __shfl_xor_sync(0xffffffff, mx1, 2));

        const float mn0 = fmaxf(m0, mx0);
        const float mn1 = fmaxf(m1, mx1);
        const float a0 = __expf(m0 - mn0);
        const float a1 = __expf(m1 - mn1);
        m0 = mn0; m1 = mn1;

        float rs0 = 0.f, rs1 = 0.f;
        #pragma unroll
        for (int nf = 0; nf < 8; nf++) {
            const float p0 = __expf(sacc[nf][0] - m0);
            const float p1 = __expf(sacc[nf][1] - m0);
            const float p2 = __expf(sacc[nf][2] - m1);
            const float p3 = __expf(sacc[nf][3] - m1);
            rs0 += p0 + p1; rs1 += p2 + p3;
            uint2 u0; u0.x = f2tf32(p0); u0.y = f2tf32(p1);
            uint2 u1; u1.x = f2tf32(p2); u1.y = f2tf32(p3);
            *reinterpret_cast<uint2*>(&Ps[(wrow + gid)     * STR + nf * 8 + 2 * tig]) = u0;
            *reinterpret_cast<uint2*>(&Ps[(wrow + gid + 8) * STR + nf * 8 + 2 * tig]) = u1;
        }
        rs0 += __shfl_xor_sync(0xffffffff, rs0, 1);
        rs0 += __shfl_xor_sync(0xffffffff, rs0, 2);
        rs1 += __shfl_xor_sync(0xffffffff, rs1, 1);
        rs1 += __shfl_xor_sync(0xffffffff, rs1, 2);
        l0 = l0 * a0 + rs0;
        l1 = l1 * a1 + rs1;

        #pragma unroll
        for (int nf = 0; nf < 8; nf++) {
            oacc[nf][0] *= a0; oacc[nf][1] *= a0;
            oacc[nf][2] *= a1; oacc[nf][3] *= a1;
        }

        __syncwarp();   // Ps rows are warp-private: order stores before loads

        // ---- O += P V ----
        #pragma unroll
        for (int kk = 0; kk < 8; kk++) {
            uint32_t a[4];
            const int pa = (wrow + gid) * STR + kk * 8;
            const int pb = (wrow + gid + 8) * STR + kk * 8;
            a[0] = Ps[pa + tig];     a[1] = Ps[pb + tig];
            a[2] = Ps[pa + tig + 4]; a[3] = Ps[pb + tig + 4];
            #pragma unroll
            for (int nf = 0; nf < 8; nf++) {
                uint32_t bv[2];
                bv[0] = Vs[(kk * 8 + tig)     * STR + nf * 8 + gid];
                bv[1] = Vs[(kk * 8 + tig + 4) * STR + nf * 8 + gid];
                mma_tf32(oacc[nf], a, bv);
            }
        }
    }

    // ---- epilogue: normalize, write [token][h*64 + d] ----
    const float inv0 = 1.f / l0;
    const float inv1 = 1.f / l1;
    float* yp0 = y + (rowbase + row0g) * N_EMBED + h * 64;
    float* yp1 = y + (rowbase + row1g) * N_EMBED + h * 64;
    #pragma unroll
    for (int nf = 0; nf < 8; nf++) {
        float2 v0, v1;
        v0.x = oacc[nf][0] * inv0; v0.y = oacc[nf][1] * inv0;
        v1.x = oacc[nf][2] * inv1; v1.y = oacc[nf][3] * inv1;
        *reinterpret_cast<float2*>(yp0 + nf * 8 + 2 * tig) = v0;
        *reinterpret_cast<float2*>(yp1 + nf * 8 + 2 * tig) = v1;
    }
}

// ---------------------------------------------------------------------------
// kernel_launch
// ---------------------------------------------------------------------------
extern "C" void kernel_launch(void* const* d_in, const int* in_sizes, int n_in,
                              void* d_out, int out_size) {
    const float* x      = (const float*)d_in[0];
    const float* W_attn = (const float*)d_in[1];
    const float* b_attn = (const float*)d_in[2];
    const float* W_proj = (const float*)d_in[3];
    const float* b_proj = (const float*)d_in[4];
    float* out = (float*)d_out;

    float* qkv = nullptr; float* yb = nullptr;
    cudaGetSymbolAddress((void**)&qkv, g_qkv);
    cudaGetSymbolAddress((void**)&yb,  g_y);

    const int fa_smem = 320 * STR * 4;   // 24320 words = 97280 bytes
    cudaFuncSetAttribute(flash_attn_mma_kernel,
                         cudaFuncAttributeMaxDynamicSharedMemorySize, fa_smem);

    // 1) QKV GEMM (tf32 mma.sync)
    {
        dim3 grid(3 * N_EMBED / 128, MROWS / 128);
        mma_gemm_kernel<<<grid, 256>>>(x, W_attn, b_attn, qkv, MROWS, 3 * N_EMBED, N_EMBED);
    }
    // 2) Causal flash attention (tf32 mma.sync)
    {
        dim3 grid(SLEN / 128, NHEADS, BATCH);
        flash_attn_mma_kernel<<<grid, 256, fa_smem>>>(qkv, yb);
    }
    // 3) Output projection (tf32 mma.sync)
    {
        dim3 grid(N_EMBED / 128, MROWS / 128);
        mma_gemm_kernel<<<grid, 256>>>(yb, W_proj, b_proj, out, MROWS, N_EMBED, N_EMBED);
    }
}